// round 6
// baseline (speedup 1.0000x reference)
#include <cuda_runtime.h>
#include <cuda_bf16.h>

// Problem constants (fixed by the dataset)
#define B 8
#define L 2048
#define H 1024
#define C 64
#define RPB 32                     // rows per block (4 chunks x 8 warps)
#define GRID (B * L / RPB)         // 512 blocks
#define BPB (L / RPB)              // 64 blocks per batch

// Persistent scratch (zero-initialized at module load; self-reset each launch)
__device__ float        g_acc[B * C];
__device__ unsigned int g_count;

// ---------------------------------------------------------------------------
// Fused kernel, R6: register-resident weights, 4-wide FMA chains, deferred
// interleaved warp reductions. Epilogue identical to R5 (fence-free atomic
// scatter + last-block finalize).
// ---------------------------------------------------------------------------
__global__ __launch_bounds__(256) void fused_kernel(
    const float* __restrict__ feature,       // [B*L, H]
    const float* __restrict__ fc_weight,     // [H]
    const float* __restrict__ fc_bias,       // [1]
    const int*   __restrict__ position_list, // [B*C*2]
    float* __restrict__ out)                 // [B*C]
{
    __shared__ float sproj[RPB];
    __shared__ int   s_src[C], s_end[C];
    __shared__ bool  is_last;
    __shared__ int   s_sink;                 // forces atomic-return consumption

    const int tid   = threadIdx.x;
    const int blk   = blockIdx.x;
    const int batch = blk / BPB;
    const int row0  = (blk % BPB) * RPB;
    const int warp  = tid >> 5;
    const int lane  = tid & 31;

    // Stage this batch's spans (512 B) into smem
    if (tid < C) {
        const int si = (batch * C + tid) * 2;
        s_src[tid] = position_list[si + 0];
        s_end[tid] = position_list[si + 1];
    }

    // Preload weights into registers: lane covers float4 idx i*32+lane,
    // identical for every row and chunk. 8 x float4 = 32 regs.
    const float4* __restrict__ wg4 = reinterpret_cast<const float4*>(fc_weight);
    float4 wr[8];
    #pragma unroll
    for (int i = 0; i < 8; i++) wr[i] = wg4[i * 32 + lane];

    // --- Stage 1: 4 chunks of 8 rows, warp-per-row; partials kept in regs ---
    const size_t base = (size_t)(batch * L + row0 + warp) * H;
    float a[4];
    #pragma unroll
    for (int c = 0; c < 4; c++) {
        const float4* __restrict__ f4 =
            reinterpret_cast<const float4*>(feature + base + (size_t)c * 8 * H);
        // 4 independent accumulation chains (depth 8 each)
        float4 acc4 = make_float4(0.f, 0.f, 0.f, 0.f);
        #pragma unroll
        for (int i = 0; i < 8; i++) {
            float4 v = f4[i * 32 + lane];
            acc4.x = fmaf(v.x, wr[i].x, acc4.x);
            acc4.y = fmaf(v.y, wr[i].y, acc4.y);
            acc4.z = fmaf(v.z, wr[i].z, acc4.z);
            acc4.w = fmaf(v.w, wr[i].w, acc4.w);
        }
        a[c] = (acc4.x + acc4.y) + (acc4.z + acc4.w);
    }

    // Deferred reductions: 4 independent shuffle chains, interleaved
    #pragma unroll
    for (int o = 16; o > 0; o >>= 1) {
        a[0] += __shfl_xor_sync(0xFFFFFFFFu, a[0], o);
        a[1] += __shfl_xor_sync(0xFFFFFFFFu, a[1], o);
        a[2] += __shfl_xor_sync(0xFFFFFFFFu, a[2], o);
        a[3] += __shfl_xor_sync(0xFFFFFFFFu, a[3], o);
    }
    if (lane == 0) {
        #pragma unroll
        for (int c = 0; c < 4; c++)
            sproj[c * 8 + warp] = a[c];
    }
    __syncthreads();

    // --- Stage 2: scatter into span accumulators (threads 0..63) ---
    if (tid < C) {
        const int src = s_src[tid];
        const int end = s_end[tid];
        int lo = src - row0; if (lo < 0) lo = 0;
        int hi = end - row0; if (hi > RPB - 1) hi = RPB - 1;
        if (lo <= hi) {
            float s = 0.0f;
            #pragma unroll
            for (int r = 0; r < RPB; r++)
                if (r >= lo && r <= hi) s += sproj[r];
            // Value-returning atomic: L2 completion observed before the
            // (never-true) predicate below can be evaluated -> release
            // ordering for the g_count arrival without MEMBAR/CCTL.
            float old = atomicAdd(&g_acc[batch * C + tid], s);
            if (__float_as_uint(old) == 0xDEADBEEFu) s_sink = 1;
        }
    }
    __syncthreads();   // all scatter atomics of this block have completed

    // --- Stage 3: arrive; last block finalizes ---
    if (tid == 0) {
        unsigned int prev = atomicAdd(&g_count, 1u);
        is_last = (prev == GRID - 1);
    }
    __syncthreads();

    if (is_last) {
        const float bias = fc_bias[0];
        #pragma unroll
        for (int k = 0; k < 2; k++) {
            const int i = tid + k * 256;     // 0..511
            const int src = position_list[i * 2 + 0];
            const int end = position_list[i * 2 + 1];
            const float v = __ldcg(&g_acc[i]);        // L2-coherent read
            out[i] = v / (float)(end - src + 1) + bias;
            __stcg(&g_acc[i], 0.0f);                  // reset for next launch
        }
        if (tid == 0) g_count = 0u;
    }
}

// ---------------------------------------------------------------------------
extern "C" void kernel_launch(void* const* d_in, const int* in_sizes, int n_in,
                              void* d_out, int out_size) {
    const float* feature       = (const float*)d_in[0];  // [B,L,H] f32
    const float* fc_weight     = (const float*)d_in[1];  // [1,H]   f32
    const float* fc_bias       = (const float*)d_in[2];  // [1]     f32
    const int*   position_list = (const int*)  d_in[3];  // [B,C,2] i32
    float* out = (float*)d_out;                          // [B*C,1] f32

    fused_kernel<<<GRID, 256>>>(feature, fc_weight, fc_bias,
                                position_list, out);
}